// round 4
// baseline (speedup 1.0000x reference)
#include <cuda_runtime.h>

// LearnableWatershedWithSDF — exact closed form.
//
// The reference's flood loop is p <- softmax(avgpool3(p) + bias), bias being
// channel-constant per pixel (softmax shift-invariant => bias is a no-op). The
// iteration contracts channel spread by ~16x per step; within ~10-12 of the 50
// iterations every pixel reaches the EXACT fp32 fixed point (all 16 probs
// identically 1/16: logit differences underflow to 0, exp(0)=1). argmax with
// first-index ties (jnp.argmax) of exact-uniform = 0 everywhere, for ANY input.
//
// Empirically confirmed: a faithful 50-iteration fp32 implementation AND a
// 16-iteration __expf implementation both gave rel_err == 0.0 (bit-identical
// int labels) vs the JAX reference. The function is identically zero, so the
// fastest correct kernel is a single 2 MB memset node in the captured graph.

extern "C" void kernel_launch(void* const* d_in, const int* in_sizes, int n_in,
                              void* d_out, int out_size) {
    (void)d_in; (void)in_sizes; (void)n_in;
    // int32 output; all-zero labels. Captured as a single graph memset node.
    cudaMemsetAsync(d_out, 0, (size_t)out_size * sizeof(int), 0);
}

// round 5
// speedup vs baseline: 1.1718x; 1.1718x over previous
#include <cuda_runtime.h>

// LearnableWatershedWithSDF — exact closed form.
//
// The reference's flood loop is p <- softmax(avgpool3(p) + bias), bias being
// channel-constant per pixel (softmax is shift-invariant => bias is a no-op).
// The iteration contracts channel logit spread by ~16x per step; within ~10-12
// of the 50 iterations every pixel hits the EXACT fp32 fixed point (all 16
// probs identically 1/16: logit differences underflow to 0, exp(0)=1, 0.0625
// exact in binary). jnp.argmax (first-index ties) of exact-uniform = 0 at
// every pixel, for ANY input. Confirmed empirically: both a faithful
// 50-iteration fp32 implementation and a 16-iteration __expf implementation
// returned rel_err == 0.0 (bit-identical labels) vs the JAX reference.
// The function is identically zero; the kernel is a 2 MB zero-fill.
//
// R3 data: one-STG-per-thread fill (512 blocks) ran 3.87us at issue=8.8% —
// launch-ramp dominated. R4 data: a graph memset node is SLOWER (6.1us) than a
// kernel node. So: one kernel node, 4x fewer blocks, 4 back-to-back STG.128
// per thread, no predication on the exact-fit path.

// Exact-fit: each block fills 4096 ints (16 KB); each thread 4 consecutive int4.
__global__ __launch_bounds__(256) void k_zero_exact(int4* __restrict__ out) {
    const int4 z = make_int4(0, 0, 0, 0);
    int4* p = out + (size_t)blockIdx.x * 1024 + threadIdx.x * 4;
    p[0] = z; p[1] = z; p[2] = z; p[3] = z;
}

// Generic fallback: grid-stride int fill (any out_size).
__global__ __launch_bounds__(256) void k_zero_any(int* __restrict__ out, int n) {
    for (int i = blockIdx.x * 256 + threadIdx.x; i < n; i += gridDim.x * 256)
        out[i] = 0;
}

extern "C" void kernel_launch(void* const* d_in, const int* in_sizes, int n_in,
                              void* d_out, int out_size) {
    (void)d_in; (void)in_sizes; (void)n_in;
    const int QUANT = 4096;                      // ints per block on fast path
    if ((out_size & (QUANT - 1)) == 0 && out_size > 0) {
        k_zero_exact<<<out_size / QUANT, 256>>>((int4*)d_out);
    } else {
        int blocks = (out_size + 255) / 256;
        if (blocks > 1024) blocks = 1024;
        if (blocks < 1) blocks = 1;
        k_zero_any<<<blocks, 256>>>((int*)d_out, out_size);
    }
}